// round 1
// baseline (speedup 1.0000x reference)
#include <cuda_runtime.h>
#include <cuda_bf16.h>
#include <math.h>

#define NN 10000
#define EE 160000
#define INF_ 128
#define DD 64
#define HH 4
#define NB 31

// ---------------- device scratch (static, no allocation) ----------------
__device__ float d_B[128 * 1024];        // combined weights: [h | Q1 | Q2 | Q3] blocks, 128 x 1024
__device__ float d_C[(size_t)NN * 1024]; // per-node: h(256) | Q1(256) | Q2(256) | Q3(256)
__device__ float d_M[12 * 64 * 64];      // M_m[h] = A_top @ F_part
__device__ float d_T[12 * 32 * 64];      // T_m[h][idx][d]
__device__ int   d_deg[NN + 1];
__device__ int   d_off[NN + 1];
__device__ int   d_cur[NN];
__device__ int   d_es[EE];

// ---------------- helpers ----------------
__device__ __forceinline__ float fast_tanh(float x) {
    float cx = fminf(fmaxf(x, -15.f), 15.f);
    float e  = __expf(2.f * cx);
    return __fdividef(e - 1.f, e + 1.f);
}

__device__ __forceinline__ int bucket(float x, const float* b) {
    // #{ i : b[i] < x }, b monotone increasing, 31 entries
    int i = (int)ceilf((x - 0.1f) * 10.f);
    i = max(0, min(31, i));
    while (i > 0 && b[i - 1] >= x) --i;
    while (i < 31 && b[i] < x) ++i;
    return i;
}

// ---------------- CSR build ----------------
__global__ void zero_deg_kernel() {
    int i = blockIdx.x * blockDim.x + threadIdx.x;
    if (i <= NN) d_deg[i] = 0;
}

__global__ void hist_kernel(const int* __restrict__ dst) {
    int e = blockIdx.x * blockDim.x + threadIdx.x;
    if (e < EE) atomicAdd(&d_deg[dst[e]], 1);
}

__global__ void scan_kernel() {
    __shared__ int s[1024];
    __shared__ int sc_carry;
    int tid = threadIdx.x;
    if (tid == 0) sc_carry = 0;
    __syncthreads();
    for (int base = 0; base < 10240; base += 1024) {
        int idx = base + tid;
        int v = (idx < NN) ? d_deg[idx] : 0;
        int x = v;
        #pragma unroll
        for (int off = 1; off < 1024; off <<= 1) {
            s[tid] = x; __syncthreads();
            if (tid >= off) x += s[tid - off];
            __syncthreads();
        }
        int carry = sc_carry;
        if (idx < NN) { d_off[idx] = carry + x - v; d_cur[idx] = carry + x - v; }
        __syncthreads();
        if (tid == 1023) sc_carry = carry + x;
        __syncthreads();
    }
    if (tid == 0) d_off[NN] = sc_carry;
}

__global__ void scatter_kernel(const int* __restrict__ dst) {
    int e = blockIdx.x * blockDim.x + threadIdx.x;
    if (e < EE) {
        int p = atomicAdd(&d_cur[dst[e]], 1);
        d_es[p] = e;
    }
}

// ---------------- precompute M and T (12 blocks = m*4+h) ----------------
__global__ void prep_kernel(const float* __restrict__ fc1, const float* __restrict__ fc2,
                            const float* __restrict__ fc3, const float* __restrict__ fcF,
                            const float* __restrict__ G, const float* __restrict__ emb) {
    int bx = blockIdx.x;
    int m = bx / HH, h = bx % HH;
    const float* A = (m == 0 ? fc1 : (m == 1 ? fc2 : fc3)) + (size_t)h * 128 * 64; // (128,64)
    const float* F = fcF + (size_t)h * 192 * 64 + (size_t)m * 64 * 64;             // rows [64m,64m+64)
    __shared__ float sAF[64 * 64];
    __shared__ float sGA[32 * 64];
    int tid = threadIdx.x;

    // M = A_top @ F  (64x64)
    for (int o = tid; o < 64 * 64; o += 256) {
        int k = o >> 6, d = o & 63;
        float acc = 0.f;
        for (int c = 0; c < 64; ++c) acc += A[k * 64 + c] * F[c * 64 + d];
        d_M[bx * 4096 + o] = acc;
    }
    // AF = A_bot @ F  (64x64)
    for (int o = tid; o < 64 * 64; o += 256) {
        int j = o >> 6, d = o & 63;
        float acc = 0.f;
        for (int c = 0; c < 64; ++c) acc += A[(64 + j) * 64 + c] * F[c * 64 + d];
        sAF[o] = acc;
    }
    __syncthreads();
    // GA = G[h] @ AF  (32x64)
    const float* Gh = G + (size_t)h * 32 * 64;
    for (int o = tid; o < 32 * 64; o += 256) {
        int k = o >> 6, d = o & 63;
        float acc = 0.f;
        for (int j = 0; j < 64; ++j) acc += Gh[k * 64 + j] * sAF[j * 64 + d];
        sGA[o] = acc;
    }
    __syncthreads();
    // T = embed(32x32) @ GA  (32x64)
    for (int o = tid; o < 32 * 64; o += 256) {
        int i = o >> 6, d = o & 63;
        float acc = 0.f;
        for (int k = 0; k < 32; ++k) acc += emb[i * 32 + k] * sGA[k * 64 + d];
        d_T[bx * 2048 + o] = acc;
    }
}

// ---------------- build combined B = [W_fc | W_fc@M1 | W_fc@M2 | W_fc@M3] ----------------
__global__ void buildB_kernel(const float* __restrict__ wfc) {
    int bx = blockIdx.x;
    int m = bx / HH, h = bx % HH;
    const float* M = d_M + bx * 4096;
    int tid = threadIdx.x;
    for (int o = tid; o < 128 * 64; o += 256) {
        int k = o >> 6, d = o & 63;
        float acc = 0.f;
        for (int j = 0; j < 64; ++j) acc += wfc[k * 256 + h * 64 + j] * M[j * 64 + d];
        d_B[k * 1024 + 256 + m * 256 + h * 64 + d] = acc;
    }
    if (m == 0) {
        for (int o = tid; o < 128 * 64; o += 256) {
            int k = o >> 6, d = o & 63;
            d_B[k * 1024 + h * 64 + d] = wfc[k * 256 + h * 64 + d];
        }
    }
}

// ---------------- node GEMM: C[N,1024] = feat[N,128] @ B[128,1024] ----------------
#define BM 64
#define BN 64
#define BK 16
__global__ void gemm_kernel(const float* __restrict__ A) {
    __shared__ float As[BK][BM];
    __shared__ float Bs[BK][BN];
    int bx = blockIdx.x;  // 16 column tiles
    int by = blockIdx.y;  // row tiles
    int tid = threadIdx.x;
    int tx = tid & 15, ty = tid >> 4;
    float acc[4][4] = {};
    int rowBase = by * BM;
    for (int k0 = 0; k0 < 128; k0 += BK) {
        for (int i = tid; i < BM * BK; i += 256) {
            int r = i / BK, c = i % BK;
            int row = rowBase + r;
            As[c][r] = (row < NN) ? A[row * 128 + k0 + c] : 0.f;
        }
        for (int i = tid; i < BK * BN; i += 256) {
            int r = i / BN, c = i % BN;
            Bs[r][c] = d_B[(k0 + r) * 1024 + bx * BN + c];
        }
        __syncthreads();
        #pragma unroll
        for (int k = 0; k < BK; ++k) {
            float a[4], b[4];
            #pragma unroll
            for (int i = 0; i < 4; ++i) a[i] = As[k][ty * 4 + i];
            #pragma unroll
            for (int j = 0; j < 4; ++j) b[j] = Bs[k][tx * 4 + j];
            #pragma unroll
            for (int i = 0; i < 4; ++i)
                #pragma unroll
                for (int j = 0; j < 4; ++j) acc[i][j] += a[i] * b[j];
        }
        __syncthreads();
    }
    for (int i = 0; i < 4; ++i) {
        int row = rowBase + ty * 4 + i;
        if (row < NN) {
            #pragma unroll
            for (int j = 0; j < 4; ++j)
                d_C[(size_t)row * 1024 + bx * BN + tx * 4 + j] = acc[i][j];
        }
    }
}

// ---------------- edge phase: one block per dst, one warp per head ----------------
__global__ void edge_kernel(const float* __restrict__ pos, const int* __restrict__ srcA,
                            const int* __restrict__ interA, const float* __restrict__ ao,
                            const float* __restrict__ bnds, float* __restrict__ out) {
    int v = blockIdx.x;
    int tid = threadIdx.x;
    int h = tid >> 5, lane = tid & 31;
    __shared__ int   sE[512];
    __shared__ float sFT[4][64];
    __shared__ float sB[NB];
    if (tid < NB) sB[tid] = bnds[tid];

    int beg = d_off[v], end = d_off[v + 1];
    int deg = end - beg;
    if (tid == 0 && deg > 0) {
        int d2 = min(deg, 512);
        for (int i = 0; i < d2; ++i) sE[i] = d_es[beg + i];
        for (int i = 1; i < d2; ++i) {  // stable ascending order -> deterministic sums
            int key = sE[i]; int j = i - 1;
            while (j >= 0 && sE[j] > key) { sE[j + 1] = sE[j]; --j; }
            sE[j + 1] = key;
        }
    }
    __syncthreads();

    float dpx = pos[v * 3 + 0], dpy = pos[v * 3 + 1], dpz = pos[v * 3 + 2];
    const float* Cv = d_C + (size_t)v * 1024;
    float2 q3  = ((const float2*)(Cv + 768 + h * 64))[lane];
    float2 aov = ((const float2*)(ao + h * 64))[lane];

    float mx = -3.4e38f, den = 0.f;
    float accx = 0.f, accy = 0.f;

    for (int i = 0; i < deg; ++i) {
        int e  = (deg <= 512) ? sE[i] : d_es[beg + i];
        int s  = srcA[e];
        int it = interA[e * HH + h];
        const float* sp = pos + (size_t)s * 3;
        const float* ip = pos + (size_t)it * 3;
        float sx = sp[0], sy = sp[1], sz = sp[2];
        float ix = ip[0], iy = ip[1], iz = ip[2];
        float d1 = sqrtf((dpx - sx) * (dpx - sx) + (dpy - sy) * (dpy - sy) + (dpz - sz) * (dpz - sz));
        float d2 = sqrtf((dpx - ix) * (dpx - ix) + (dpy - iy) * (dpy - iy) + (dpz - iz) * (dpz - iz));
        float d3 = sqrtf((sx - ix) * (sx - ix) + (sy - iy) * (sy - iy) + (sz - iz) * (sz - iz));
        int i1 = bucket(d1, sB), i2 = bucket(d2, sB), i3 = bucket(d3, sB);

        const float* Cs = d_C + (size_t)s  * 1024;
        const float* Ci = d_C + (size_t)it * 1024;
        float2 q1 = ((const float2*)(Cs + 256 + h * 64))[lane];
        float2 q2 = ((const float2*)(Ci + 512 + h * 64))[lane];
        float2 t1 = ((const float2*)(d_T + ((0 * HH + h) * 32 + i1) * 64))[lane];
        float2 t2 = ((const float2*)(d_T + ((1 * HH + h) * 32 + i2) * 64))[lane];
        float2 t3 = ((const float2*)(d_T + ((2 * HH + h) * 32 + i3) * 64))[lane];

        float zx = q1.x + q2.x + q3.x + t1.x + t2.x + t3.x;
        float zy = q1.y + q2.y + q3.y + t1.y + t2.y + t3.y;
        float sc = fast_tanh(zx) * aov.x + fast_tanh(zy) * aov.y;
        #pragma unroll
        for (int o = 16; o > 0; o >>= 1) sc += __shfl_xor_sync(0xffffffffu, sc, o);

        float nm = fmaxf(mx, sc);
        float scale = __expf(mx - nm);
        float w = __expf(sc - nm);
        float2 hs = ((const float2*)(Cs + h * 64))[lane];
        den  = den  * scale + w;
        accx = accx * scale + w * hs.x;
        accy = accy * scale + w * hs.y;
        mx = nm;
    }

    float inv = (den > 0.f) ? 1.0f / den : 0.f;
    sFT[h][lane * 2 + 0] = accx * inv;
    sFT[h][lane * 2 + 1] = accy * inv;
    __syncthreads();
    if (tid < 64)
        out[(size_t)v * 64 + tid] = 0.25f * (sFT[0][tid] + sFT[1][tid] + sFT[2][tid] + sFT[3][tid]);
}

// ---------------- launch ----------------
extern "C" void kernel_launch(void* const* d_in, const int* in_sizes, int n_in,
                              void* d_out, int out_size) {
    // Disambiguate input ordering via sizes: dict order has src (160000) at idx 2,
    // signature order has W_fc (32768) at idx 2.
    int i_feat = 0, i_loc = 1, i_src, i_dst, i_inter, i_wfc, i_emb, i_G,
        i_fc1, i_fc2, i_fc3, i_fc, i_ao, i_b;
    if (in_sizes[2] == EE) { // dict order
        i_src = 2; i_dst = 3; i_inter = 4; i_wfc = 5; i_emb = 6; i_G = 7;
        i_fc1 = 8; i_fc2 = 9; i_fc3 = 10; i_fc = 11; i_ao = 12; i_b = 13;
    } else {                 // signature order
        i_wfc = 2; i_emb = 3; i_G = 4; i_fc1 = 5; i_fc2 = 6; i_fc3 = 7;
        i_fc = 8; i_ao = 9; i_b = 10; i_src = 11; i_dst = 12; i_inter = 13;
    }

    const float* feat  = (const float*)d_in[i_feat];
    const float* pos   = (const float*)d_in[i_loc];
    const int*   src   = (const int*)  d_in[i_src];
    const int*   dst   = (const int*)  d_in[i_dst];
    const int*   inter = (const int*)  d_in[i_inter];
    const float* wfc   = (const float*)d_in[i_wfc];
    const float* emb   = (const float*)d_in[i_emb];
    const float* G     = (const float*)d_in[i_G];
    const float* fc1   = (const float*)d_in[i_fc1];
    const float* fc2   = (const float*)d_in[i_fc2];
    const float* fc3   = (const float*)d_in[i_fc3];
    const float* fcF   = (const float*)d_in[i_fc];
    const float* ao    = (const float*)d_in[i_ao];
    const float* bnds  = (const float*)d_in[i_b];
    float* out = (float*)d_out;

    zero_deg_kernel<<<(NN + 256) / 256, 256>>>();
    hist_kernel<<<(EE + 255) / 256, 256>>>(dst);
    scan_kernel<<<1, 1024>>>();
    scatter_kernel<<<(EE + 255) / 256, 256>>>(dst);
    prep_kernel<<<12, 256>>>(fc1, fc2, fc3, fcF, G, emb);
    buildB_kernel<<<12, 256>>>(wfc);
    gemm_kernel<<<dim3(16, (NN + BM - 1) / BM), 256>>>(feat);
    edge_kernel<<<NN, 128>>>(pos, src, inter, ao, bnds, out);
}

// round 2
// speedup vs baseline: 1.1209x; 1.1209x over previous
#include <cuda_runtime.h>
#include <cuda_bf16.h>
#include <math.h>

#define NN 10000
#define EE 160000
#define HH 4
#define NB 31

// ---------------- device scratch (static, no allocation) ----------------
__device__ float d_B[128 * 1024];        // combined weights: [h | Q1 | Q2 | Q3], 128 x 1024
__device__ float d_C[(size_t)NN * 1024]; // per-node: h(256) | Q1(256) | Q2(256) | Q3(256)
__device__ float d_M[12 * 64 * 64];      // M_m[h] = A_top @ F_part
__device__ float d_T[12 * 32 * 64];      // T_m[h][idx][d]
__device__ float d_sc[(size_t)EE * HH];  // per-(edge,head) attention logits
__device__ int   d_deg[NN + 1];
__device__ int   d_off[NN + 1];
__device__ int   d_cur[NN];
__device__ int   d_es[EE];

// ---------------- helpers ----------------
__device__ __forceinline__ float fast_tanh(float x) {
    float cx = fminf(fmaxf(x, -15.f), 15.f);
    float e  = __expf(2.f * cx);
    return __fdividef(e - 1.f, e + 1.f);
}

__device__ __forceinline__ int bucket(float x, const float* b) {
    // #{ i : b[i] < x }, b monotone increasing, 31 entries (exact vs searchsorted)
    int i = (int)ceilf((x - 0.1f) * 10.f);
    i = max(0, min(31, i));
    while (i > 0 && b[i - 1] >= x) --i;
    while (i < 31 && b[i] < x) ++i;
    return i;
}

// ---------------- CSR build ----------------
__global__ void zero_deg_kernel() {
    int i = blockIdx.x * blockDim.x + threadIdx.x;
    if (i <= NN) d_deg[i] = 0;
}

__global__ void hist_kernel(const int* __restrict__ dst) {
    int e = blockIdx.x * blockDim.x + threadIdx.x;
    if (e < EE) atomicAdd(&d_deg[dst[e]], 1);
}

// single block, 1024 threads, 10 elements/thread, warp-shfl block scan
__global__ void scan_kernel() {
    __shared__ int warpsum[32];
    int tid = threadIdx.x;
    int lane = tid & 31, wid = tid >> 5;
    int base = tid * 10;
    int loc[10];
    int s = 0;
    #pragma unroll
    for (int j = 0; j < 10; ++j) {
        int idx = base + j;
        int v = (idx < NN) ? d_deg[idx] : 0;
        loc[j] = s;
        s += v;
    }
    int x = s;
    #pragma unroll
    for (int off = 1; off < 32; off <<= 1) {
        int y = __shfl_up_sync(0xffffffffu, x, off);
        if (lane >= off) x += y;
    }
    if (lane == 31) warpsum[wid] = x;
    __syncthreads();
    if (wid == 0) {
        int t = warpsum[lane];
        #pragma unroll
        for (int off = 1; off < 32; off <<= 1) {
            int y = __shfl_up_sync(0xffffffffu, t, off);
            if (lane >= off) t += y;
        }
        warpsum[lane] = t;
    }
    __syncthreads();
    int warpbase = (wid > 0) ? warpsum[wid - 1] : 0;
    int excl = warpbase + x - s;
    #pragma unroll
    for (int j = 0; j < 10; ++j) {
        int idx = base + j;
        if (idx < NN) { d_off[idx] = excl + loc[j]; d_cur[idx] = excl + loc[j]; }
    }
    if (tid == 0) d_off[NN] = warpsum[31];
}

__global__ void scatter_kernel(const int* __restrict__ dst) {
    int e = blockIdx.x * blockDim.x + threadIdx.x;
    if (e < EE) {
        int p = atomicAdd(&d_cur[dst[e]], 1);
        d_es[p] = e;
    }
}

// ---------------- precompute M and T (12 blocks = m*4+h) ----------------
__global__ void prep_kernel(const float* __restrict__ fc1, const float* __restrict__ fc2,
                            const float* __restrict__ fc3, const float* __restrict__ fcF,
                            const float* __restrict__ G, const float* __restrict__ emb) {
    int bx = blockIdx.x;
    int m = bx / HH, h = bx % HH;
    const float* A = (m == 0 ? fc1 : (m == 1 ? fc2 : fc3)) + (size_t)h * 128 * 64;
    const float* F = fcF + (size_t)h * 192 * 64 + (size_t)m * 64 * 64;
    __shared__ float sAF[64 * 64];
    __shared__ float sGA[32 * 64];
    int tid = threadIdx.x;

    for (int o = tid; o < 64 * 64; o += 256) {  // M = A_top @ F
        int k = o >> 6, d = o & 63;
        float acc = 0.f;
        for (int c = 0; c < 64; ++c) acc += A[k * 64 + c] * F[c * 64 + d];
        d_M[bx * 4096 + o] = acc;
    }
    for (int o = tid; o < 64 * 64; o += 256) {  // AF = A_bot @ F
        int j = o >> 6, d = o & 63;
        float acc = 0.f;
        for (int c = 0; c < 64; ++c) acc += A[(64 + j) * 64 + c] * F[c * 64 + d];
        sAF[o] = acc;
    }
    __syncthreads();
    const float* Gh = G + (size_t)h * 32 * 64;  // GA = G[h] @ AF
    for (int o = tid; o < 32 * 64; o += 256) {
        int k = o >> 6, d = o & 63;
        float acc = 0.f;
        for (int j = 0; j < 64; ++j) acc += Gh[k * 64 + j] * sAF[j * 64 + d];
        sGA[o] = acc;
    }
    __syncthreads();
    for (int o = tid; o < 32 * 64; o += 256) {  // T = embed @ GA
        int i = o >> 6, d = o & 63;
        float acc = 0.f;
        for (int k = 0; k < 32; ++k) acc += emb[i * 32 + k] * sGA[k * 64 + d];
        d_T[bx * 2048 + o] = acc;
    }
}

// ---------------- build combined B = [W_fc | W_fc@M1 | W_fc@M2 | W_fc@M3] ----------------
__global__ void buildB_kernel(const float* __restrict__ wfc) {
    int bx = blockIdx.x;
    int m = bx / HH, h = bx % HH;
    const float* M = d_M + bx * 4096;
    int tid = threadIdx.x;
    for (int o = tid; o < 128 * 64; o += 256) {
        int k = o >> 6, d = o & 63;
        float acc = 0.f;
        for (int j = 0; j < 64; ++j) acc += wfc[k * 256 + h * 64 + j] * M[j * 64 + d];
        d_B[k * 1024 + 256 + m * 256 + h * 64 + d] = acc;
    }
    if (m == 0) {
        for (int o = tid; o < 128 * 64; o += 256) {
            int k = o >> 6, d = o & 63;
            d_B[k * 1024 + h * 64 + d] = wfc[k * 256 + h * 64 + d];
        }
    }
}

// ---------------- node GEMM: C[N,1024] = feat[N,128] @ B[128,1024] ----------------
// 128x128 tile, 256 threads, 8x8 per thread, BK=16
__global__ void gemm_kernel(const float* __restrict__ A) {
    __shared__ float As[16][128];
    __shared__ float Bs[16][128];
    int bx = blockIdx.x;  // 8 column tiles of 128
    int by = blockIdx.y;  // row tiles
    int tid = threadIdx.x;
    int tx = tid & 15, ty = tid >> 4;
    float acc[8][8] = {};
    int rowBase = by * 128;
    for (int k0 = 0; k0 < 128; k0 += 16) {
        // A tile: 128 rows x 16 k. Each thread: 8 consecutive k in one row (2 float4).
        {
            int r = tid >> 1;
            int c = (tid & 1) * 8;
            int row = rowBase + r;
            float4 v0, v1;
            if (row < NN) {
                v0 = *(const float4*)(A + (size_t)row * 128 + k0 + c);
                v1 = *(const float4*)(A + (size_t)row * 128 + k0 + c + 4);
            } else {
                v0 = make_float4(0.f, 0.f, 0.f, 0.f);
                v1 = v0;
            }
            As[c + 0][r] = v0.x; As[c + 1][r] = v0.y; As[c + 2][r] = v0.z; As[c + 3][r] = v0.w;
            As[c + 4][r] = v1.x; As[c + 5][r] = v1.y; As[c + 6][r] = v1.z; As[c + 7][r] = v1.w;
        }
        // B tile: 16 k x 128 n. Each thread: 8 consecutive n (2 float4).
        {
            int i = tid * 8;
            int r = i >> 7, c = i & 127;
            const float* src = d_B + (size_t)(k0 + r) * 1024 + bx * 128 + c;
            float4 v0 = *(const float4*)(src);
            float4 v1 = *(const float4*)(src + 4);
            *(float4*)(&Bs[r][c]) = v0;
            *(float4*)(&Bs[r][c + 4]) = v1;
        }
        __syncthreads();
        #pragma unroll
        for (int k = 0; k < 16; ++k) {
            float a[8], b[8];
            *(float4*)(a)     = *(const float4*)(&As[k][ty * 8]);
            *(float4*)(a + 4) = *(const float4*)(&As[k][ty * 8 + 4]);
            *(float4*)(b)     = *(const float4*)(&Bs[k][tx * 8]);
            *(float4*)(b + 4) = *(const float4*)(&Bs[k][tx * 8 + 4]);
            #pragma unroll
            for (int i = 0; i < 8; ++i)
                #pragma unroll
                for (int j = 0; j < 8; ++j) acc[i][j] += a[i] * b[j];
        }
        __syncthreads();
    }
    #pragma unroll
    for (int i = 0; i < 8; ++i) {
        int row = rowBase + ty * 8 + i;
        if (row < NN) {
            float* dstp = d_C + (size_t)row * 1024 + bx * 128 + tx * 8;
            *(float4*)(dstp)     = make_float4(acc[i][0], acc[i][1], acc[i][2], acc[i][3]);
            *(float4*)(dstp + 4) = make_float4(acc[i][4], acc[i][5], acc[i][6], acc[i][7]);
        }
    }
}

// ---------------- score kernel: one block per edge, one warp per head ----------------
__global__ void score_kernel(const float* __restrict__ pos, const int* __restrict__ srcA,
                             const int* __restrict__ dstA, const int* __restrict__ interA,
                             const float* __restrict__ ao, const float* __restrict__ bnds) {
    int e = blockIdx.x;
    int tid = threadIdx.x;
    int h = tid >> 5, lane = tid & 31;
    __shared__ float sB[NB];
    if (tid < NB) sB[tid] = bnds[tid];
    __syncthreads();

    int s  = srcA[e];
    int v  = dstA[e];
    int it = interA[e * HH + h];

    const float* sp = pos + (size_t)s * 3;
    const float* dp = pos + (size_t)v * 3;
    const float* ip = pos + (size_t)it * 3;
    float sx = sp[0], sy = sp[1], sz = sp[2];
    float dx = dp[0], dy = dp[1], dz = dp[2];
    float ix = ip[0], iy = ip[1], iz = ip[2];
    float d1 = sqrtf((dx - sx) * (dx - sx) + (dy - sy) * (dy - sy) + (dz - sz) * (dz - sz));
    float d2 = sqrtf((dx - ix) * (dx - ix) + (dy - iy) * (dy - iy) + (dz - iz) * (dz - iz));
    float d3 = sqrtf((sx - ix) * (sx - ix) + (sy - iy) * (sy - iy) + (sz - iz) * (sz - iz));
    int i1 = bucket(d1, sB), i2 = bucket(d2, sB), i3 = bucket(d3, sB);

    const float* Cs = d_C + (size_t)s  * 1024;
    const float* Ci = d_C + (size_t)it * 1024;
    const float* Cv = d_C + (size_t)v  * 1024;
    float2 q1 = ((const float2*)(Cs + 256 + h * 64))[lane];
    float2 q2 = ((const float2*)(Ci + 512 + h * 64))[lane];
    float2 q3 = ((const float2*)(Cv + 768 + h * 64))[lane];
    float2 t1 = ((const float2*)(d_T + ((0 * HH + h) * 32 + i1) * 64))[lane];
    float2 t2 = ((const float2*)(d_T + ((1 * HH + h) * 32 + i2) * 64))[lane];
    float2 t3 = ((const float2*)(d_T + ((2 * HH + h) * 32 + i3) * 64))[lane];
    float2 aov = ((const float2*)(ao + h * 64))[lane];

    float zx = q1.x + q2.x + q3.x + t1.x + t2.x + t3.x;
    float zy = q1.y + q2.y + q3.y + t1.y + t2.y + t3.y;
    float sc = fast_tanh(zx) * aov.x + fast_tanh(zy) * aov.y;
    #pragma unroll
    for (int o = 16; o > 0; o >>= 1) sc += __shfl_xor_sync(0xffffffffu, sc, o);
    if (lane == 0) d_sc[(size_t)e * HH + h] = sc;
}

// ---------------- aggregation: one block per dst, one warp per head ----------------
__global__ void agg_kernel(const int* __restrict__ srcA, float* __restrict__ out) {
    int v = blockIdx.x;
    int tid = threadIdx.x;
    int h = tid >> 5, lane = tid & 31;
    __shared__ float sFT[4][64];

    int beg = d_off[v], end = d_off[v + 1];

    float mx = -3.4e38f, den = 0.f;
    float accx = 0.f, accy = 0.f;

    for (int i = beg; i < end; ++i) {
        int e = d_es[i];
        float sc = d_sc[(size_t)e * HH + h];
        int s = srcA[e];
        float2 hs = ((const float2*)(d_C + (size_t)s * 1024 + h * 64))[lane];
        float nm = fmaxf(mx, sc);
        float scale = __expf(mx - nm);
        float w = __expf(sc - nm);
        den  = den  * scale + w;
        accx = accx * scale + w * hs.x;
        accy = accy * scale + w * hs.y;
        mx = nm;
    }

    float inv = (den > 0.f) ? 1.0f / den : 0.f;
    sFT[h][lane * 2 + 0] = accx * inv;
    sFT[h][lane * 2 + 1] = accy * inv;
    __syncthreads();
    if (tid < 64)
        out[(size_t)v * 64 + tid] = 0.25f * (sFT[0][tid] + sFT[1][tid] + sFT[2][tid] + sFT[3][tid]);
}

// ---------------- launch ----------------
extern "C" void kernel_launch(void* const* d_in, const int* in_sizes, int n_in,
                              void* d_out, int out_size) {
    int i_feat = 0, i_loc = 1, i_src, i_dst, i_inter, i_wfc, i_emb, i_G,
        i_fc1, i_fc2, i_fc3, i_fc, i_ao, i_b;
    if (in_sizes[2] == EE) { // dict order
        i_src = 2; i_dst = 3; i_inter = 4; i_wfc = 5; i_emb = 6; i_G = 7;
        i_fc1 = 8; i_fc2 = 9; i_fc3 = 10; i_fc = 11; i_ao = 12; i_b = 13;
    } else {                 // signature order
        i_wfc = 2; i_emb = 3; i_G = 4; i_fc1 = 5; i_fc2 = 6; i_fc3 = 7;
        i_fc = 8; i_ao = 9; i_b = 10; i_src = 11; i_dst = 12; i_inter = 13;
    }

    const float* feat  = (const float*)d_in[i_feat];
    const float* pos   = (const float*)d_in[i_loc];
    const int*   src   = (const int*)  d_in[i_src];
    const int*   dst   = (const int*)  d_in[i_dst];
    const int*   inter = (const int*)  d_in[i_inter];
    const float* wfc   = (const float*)d_in[i_wfc];
    const float* emb   = (const float*)d_in[i_emb];
    const float* G     = (const float*)d_in[i_G];
    const float* fc1   = (const float*)d_in[i_fc1];
    const float* fc2   = (const float*)d_in[i_fc2];
    const float* fc3   = (const float*)d_in[i_fc3];
    const float* fcF   = (const float*)d_in[i_fc];
    const float* ao    = (const float*)d_in[i_ao];
    const float* bnds  = (const float*)d_in[i_b];
    float* out = (float*)d_out;

    // order chosen so gemm_kernel lands in the ncu capture slot (#4)
    zero_deg_kernel<<<(NN + 256) / 256, 256>>>();
    prep_kernel<<<12, 256>>>(fc1, fc2, fc3, fcF, G, emb);
    buildB_kernel<<<12, 256>>>(wfc);
    gemm_kernel<<<dim3(8, (NN + 127) / 128), 256>>>(feat);
    hist_kernel<<<(EE + 255) / 256, 256>>>(dst);
    scan_kernel<<<1, 1024>>>();
    scatter_kernel<<<(EE + 255) / 256, 256>>>(dst);
    score_kernel<<<EE, 128>>>(pos, src, dst, inter, ao, bnds);
    agg_kernel<<<NN, 128>>>(src, out);
}

// round 3
// speedup vs baseline: 1.1598x; 1.0346x over previous
#include <cuda_runtime.h>
#include <cuda_bf16.h>
#include <math.h>

#define NN 10000
#define EE 160000
#define HH 4
#define NB 31

// ---------------- device scratch (static, no allocation) ----------------
__device__ float d_B[128 * 1024];        // combined weights: [h | Q1 | Q2 | Q3], 128 x 1024
__device__ float d_C[(size_t)NN * 1024]; // per-node: h(256) | Q1(256) | Q2(256) | Q3(256)
__device__ float d_M[12 * 64 * 64];      // M_m[h] = A_top @ F_part
__device__ float d_T[12 * 32 * 64];      // T_m[h][idx][d]
__device__ float d_sc[(size_t)EE * HH];  // per-(edge,head) attention logits
__device__ int   d_deg[NN + 1];
__device__ int   d_off[NN + 1];
__device__ int   d_cur[NN];
__device__ int   d_es[EE];               // CSR-ordered edge ids
__device__ int   d_srcs[EE];             // CSR-ordered src node ids

// ---------------- helpers ----------------
__device__ __forceinline__ float fast_tanh(float x) {
    float cx = fminf(fmaxf(x, -15.f), 15.f);
    float e  = __expf(2.f * cx);
    return __fdividef(e - 1.f, e + 1.f);
}

__device__ __forceinline__ int bucket(float x, const float* __restrict__ b) {
    // #{ i : b[i] < x }, b monotone increasing (0.1..3.1 step 0.1), exact vs searchsorted
    int i = (int)ceilf((x - 0.1f) * 10.f);
    i = max(0, min(31, i));
    while (i > 0 && __ldg(b + i - 1) >= x) --i;
    while (i < 31 && __ldg(b + i) < x) ++i;
    return i;
}

// ---------------- CSR build ----------------
__global__ void zero_deg_kernel() {
    int i = blockIdx.x * blockDim.x + threadIdx.x;
    if (i <= NN) d_deg[i] = 0;
}

__global__ void hist_kernel(const int* __restrict__ dst) {
    int e = blockIdx.x * blockDim.x + threadIdx.x;
    if (e < EE) atomicAdd(&d_deg[dst[e]], 1);
}

// single block, 1024 threads, 10 elements/thread, warp-shfl block scan
__global__ void scan_kernel() {
    __shared__ int warpsum[32];
    int tid = threadIdx.x;
    int lane = tid & 31, wid = tid >> 5;
    int base = tid * 10;
    int loc[10];
    int s = 0;
    #pragma unroll
    for (int j = 0; j < 10; ++j) {
        int idx = base + j;
        int v = (idx < NN) ? d_deg[idx] : 0;
        loc[j] = s;
        s += v;
    }
    int x = s;
    #pragma unroll
    for (int off = 1; off < 32; off <<= 1) {
        int y = __shfl_up_sync(0xffffffffu, x, off);
        if (lane >= off) x += y;
    }
    if (lane == 31) warpsum[wid] = x;
    __syncthreads();
    if (wid == 0) {
        int t = warpsum[lane];
        #pragma unroll
        for (int off = 1; off < 32; off <<= 1) {
            int y = __shfl_up_sync(0xffffffffu, t, off);
            if (lane >= off) t += y;
        }
        warpsum[lane] = t;
    }
    __syncthreads();
    int warpbase = (wid > 0) ? warpsum[wid - 1] : 0;
    int excl = warpbase + x - s;
    #pragma unroll
    for (int j = 0; j < 10; ++j) {
        int idx = base + j;
        if (idx < NN) { d_off[idx] = excl + loc[j]; d_cur[idx] = excl + loc[j]; }
    }
    if (tid == 0) d_off[NN] = warpsum[31];
}

__global__ void scatter_kernel(const int* __restrict__ dst, const int* __restrict__ src) {
    int e = blockIdx.x * blockDim.x + threadIdx.x;
    if (e < EE) {
        int p = atomicAdd(&d_cur[dst[e]], 1);
        d_es[p] = e;
        d_srcs[p] = src[e];
    }
}

// ---------------- precompute M and T (12 blocks = m*4+h) ----------------
__global__ void prep_kernel(const float* __restrict__ fc1, const float* __restrict__ fc2,
                            const float* __restrict__ fc3, const float* __restrict__ fcF,
                            const float* __restrict__ G, const float* __restrict__ emb) {
    int bx = blockIdx.x;
    int m = bx / HH, h = bx % HH;
    const float* A = (m == 0 ? fc1 : (m == 1 ? fc2 : fc3)) + (size_t)h * 128 * 64;
    const float* F = fcF + (size_t)h * 192 * 64 + (size_t)m * 64 * 64;
    __shared__ float sAF[64 * 64];
    __shared__ float sGA[32 * 64];
    int tid = threadIdx.x;

    for (int o = tid; o < 64 * 64; o += 256) {  // M = A_top @ F
        int k = o >> 6, d = o & 63;
        float acc = 0.f;
        for (int c = 0; c < 64; ++c) acc += A[k * 64 + c] * F[c * 64 + d];
        d_M[bx * 4096 + o] = acc;
    }
    for (int o = tid; o < 64 * 64; o += 256) {  // AF = A_bot @ F
        int j = o >> 6, d = o & 63;
        float acc = 0.f;
        for (int c = 0; c < 64; ++c) acc += A[(64 + j) * 64 + c] * F[c * 64 + d];
        sAF[o] = acc;
    }
    __syncthreads();
    const float* Gh = G + (size_t)h * 32 * 64;  // GA = G[h] @ AF
    for (int o = tid; o < 32 * 64; o += 256) {
        int k = o >> 6, d = o & 63;
        float acc = 0.f;
        for (int j = 0; j < 64; ++j) acc += Gh[k * 64 + j] * sAF[j * 64 + d];
        sGA[o] = acc;
    }
    __syncthreads();
    for (int o = tid; o < 32 * 64; o += 256) {  // T = embed @ GA
        int i = o >> 6, d = o & 63;
        float acc = 0.f;
        for (int k = 0; k < 32; ++k) acc += emb[i * 32 + k] * sGA[k * 64 + d];
        d_T[bx * 2048 + o] = acc;
    }
}

// ---------------- build combined B = [W_fc | W_fc@M1 | W_fc@M2 | W_fc@M3] ----------------
__global__ void buildB_kernel(const float* __restrict__ wfc) {
    int bx = blockIdx.x;
    int m = bx / HH, h = bx % HH;
    const float* M = d_M + bx * 4096;
    int tid = threadIdx.x;
    for (int o = tid; o < 128 * 64; o += 256) {
        int k = o >> 6, d = o & 63;
        float acc = 0.f;
        for (int j = 0; j < 64; ++j) acc += wfc[k * 256 + h * 64 + j] * M[j * 64 + d];
        d_B[k * 1024 + 256 + m * 256 + h * 64 + d] = acc;
    }
    if (m == 0) {
        for (int o = tid; o < 128 * 64; o += 256) {
            int k = o >> 6, d = o & 63;
            d_B[k * 1024 + h * 64 + d] = wfc[k * 256 + h * 64 + d];
        }
    }
}

// ---------------- node GEMM: C[N,1024] = feat[N,128] @ B[128,1024] ----------------
// 128x128 tile, 256 threads, 8x8 per thread, BK=16
__global__ void __launch_bounds__(256, 2) gemm_kernel(const float* __restrict__ A) {
    __shared__ float As[16][128];
    __shared__ float Bs[16][128];
    int bx = blockIdx.x;  // 8 column tiles of 128
    int by = blockIdx.y;  // row tiles
    int tid = threadIdx.x;
    int tx = tid & 15, ty = tid >> 4;
    float acc[8][8] = {};
    int rowBase = by * 128;
    for (int k0 = 0; k0 < 128; k0 += 16) {
        {
            int r = tid >> 1;
            int c = (tid & 1) * 8;
            int row = rowBase + r;
            float4 v0, v1;
            if (row < NN) {
                v0 = *(const float4*)(A + (size_t)row * 128 + k0 + c);
                v1 = *(const float4*)(A + (size_t)row * 128 + k0 + c + 4);
            } else {
                v0 = make_float4(0.f, 0.f, 0.f, 0.f);
                v1 = v0;
            }
            As[c + 0][r] = v0.x; As[c + 1][r] = v0.y; As[c + 2][r] = v0.z; As[c + 3][r] = v0.w;
            As[c + 4][r] = v1.x; As[c + 5][r] = v1.y; As[c + 6][r] = v1.z; As[c + 7][r] = v1.w;
        }
        {
            int i = tid * 8;
            int r = i >> 7, c = i & 127;
            const float* src = d_B + (size_t)(k0 + r) * 1024 + bx * 128 + c;
            float4 v0 = *(const float4*)(src);
            float4 v1 = *(const float4*)(src + 4);
            *(float4*)(&Bs[r][c]) = v0;
            *(float4*)(&Bs[r][c + 4]) = v1;
        }
        __syncthreads();
        #pragma unroll
        for (int k = 0; k < 16; ++k) {
            float a[8], b[8];
            *(float4*)(a)     = *(const float4*)(&As[k][ty * 8]);
            *(float4*)(a + 4) = *(const float4*)(&As[k][ty * 8 + 4]);
            *(float4*)(b)     = *(const float4*)(&Bs[k][tx * 8]);
            *(float4*)(b + 4) = *(const float4*)(&Bs[k][tx * 8 + 4]);
            #pragma unroll
            for (int i = 0; i < 8; ++i)
                #pragma unroll
                for (int j = 0; j < 8; ++j) acc[i][j] += a[i] * b[j];
        }
        __syncthreads();
    }
    #pragma unroll
    for (int i = 0; i < 8; ++i) {
        int row = rowBase + ty * 8 + i;
        if (row < NN) {
            float* dstp = d_C + (size_t)row * 1024 + bx * 128 + tx * 8;
            *(float4*)(dstp)     = make_float4(acc[i][0], acc[i][1], acc[i][2], acc[i][3]);
            *(float4*)(dstp + 4) = make_float4(acc[i][4], acc[i][5], acc[i][6], acc[i][7]);
        }
    }
}

// ---------------- score kernel: 256 thr = 8 warps = 2 edges x 4 heads ----------------
__global__ void score_kernel(const float* __restrict__ pos, const int* __restrict__ srcA,
                             const int* __restrict__ dstA, const int* __restrict__ interA,
                             const float* __restrict__ ao, const float* __restrict__ bnds) {
    int wid = threadIdx.x >> 5, lane = threadIdx.x & 31;
    int e = blockIdx.x * 2 + (wid >> 2);
    int h = wid & 3;
    if (e >= EE) return;

    int s  = __ldg(srcA + e);
    int v  = __ldg(dstA + e);
    int it = __ldg(interA + (size_t)e * HH + h);

    float sx = __ldg(pos + (size_t)s * 3 + 0), sy = __ldg(pos + (size_t)s * 3 + 1), sz = __ldg(pos + (size_t)s * 3 + 2);
    float dx = __ldg(pos + (size_t)v * 3 + 0), dy = __ldg(pos + (size_t)v * 3 + 1), dz = __ldg(pos + (size_t)v * 3 + 2);
    float ix = __ldg(pos + (size_t)it * 3 + 0), iy = __ldg(pos + (size_t)it * 3 + 1), iz = __ldg(pos + (size_t)it * 3 + 2);
    float d1 = sqrtf((dx - sx) * (dx - sx) + (dy - sy) * (dy - sy) + (dz - sz) * (dz - sz));
    float d2 = sqrtf((dx - ix) * (dx - ix) + (dy - iy) * (dy - iy) + (dz - iz) * (dz - iz));
    float d3 = sqrtf((sx - ix) * (sx - ix) + (sy - iy) * (sy - iy) + (sz - iz) * (sz - iz));
    int i1 = bucket(d1, bnds), i2 = bucket(d2, bnds), i3 = bucket(d3, bnds);

    const float* Cs = d_C + (size_t)s  * 1024;
    const float* Ci = d_C + (size_t)it * 1024;
    const float* Cv = d_C + (size_t)v  * 1024;
    float2 q1 = ((const float2*)(Cs + 256 + h * 64))[lane];
    float2 q2 = ((const float2*)(Ci + 512 + h * 64))[lane];
    float2 q3 = ((const float2*)(Cv + 768 + h * 64))[lane];
    float2 t1 = ((const float2*)(d_T + ((0 * HH + h) * 32 + i1) * 64))[lane];
    float2 t2 = ((const float2*)(d_T + ((1 * HH + h) * 32 + i2) * 64))[lane];
    float2 t3 = ((const float2*)(d_T + ((2 * HH + h) * 32 + i3) * 64))[lane];
    float2 aov = ((const float2*)(ao + h * 64))[lane];

    float zx = q1.x + q2.x + q3.x + t1.x + t2.x + t3.x;
    float zy = q1.y + q2.y + q3.y + t1.y + t2.y + t3.y;
    float sc = fast_tanh(zx) * aov.x + fast_tanh(zy) * aov.y;
    #pragma unroll
    for (int o = 16; o > 0; o >>= 1) sc += __shfl_xor_sync(0xffffffffu, sc, o);
    if (lane == 0) d_sc[(size_t)e * HH + h] = sc;
}

// ---------------- aggregation: one block per dst, one warp per head ----------------
__global__ void agg_kernel(float* __restrict__ out) {
    int v = blockIdx.x;
    int tid = threadIdx.x;
    int h = tid >> 5, lane = tid & 31;
    __shared__ float sFT[4][64];

    int beg = d_off[v], end = d_off[v + 1];

    float mx = -3.4e38f, den = 0.f;
    float accx = 0.f, accy = 0.f;

    for (int c = beg; c < end; c += 32) {
        int n = min(32, end - c);
        int sL = 0; float scL = 0.f;
        if (lane < n) {
            int eL = d_es[c + lane];
            sL = d_srcs[c + lane];
            scL = d_sc[(size_t)eL * HH + h];
        }
        for (int j = 0; j < n; ++j) {
            int s    = __shfl_sync(0xffffffffu, sL, j);
            float sc = __shfl_sync(0xffffffffu, scL, j);
            float2 hs = ((const float2*)(d_C + (size_t)s * 1024 + h * 64))[lane];
            float nm = fmaxf(mx, sc);
            float scale = __expf(mx - nm);
            float w = __expf(sc - nm);
            den  = den  * scale + w;
            accx = accx * scale + w * hs.x;
            accy = accy * scale + w * hs.y;
            mx = nm;
        }
    }

    float inv = (den > 0.f) ? 1.0f / den : 0.f;
    sFT[h][lane * 2 + 0] = accx * inv;
    sFT[h][lane * 2 + 1] = accy * inv;
    __syncthreads();
    if (tid < 64)
        out[(size_t)v * 64 + tid] = 0.25f * (sFT[0][tid] + sFT[1][tid] + sFT[2][tid] + sFT[3][tid]);
}

// ---------------- launch ----------------
extern "C" void kernel_launch(void* const* d_in, const int* in_sizes, int n_in,
                              void* d_out, int out_size) {
    int i_feat = 0, i_loc = 1, i_src, i_dst, i_inter, i_wfc, i_emb, i_G,
        i_fc1, i_fc2, i_fc3, i_fc, i_ao, i_b;
    if (in_sizes[2] == EE) { // dict order
        i_src = 2; i_dst = 3; i_inter = 4; i_wfc = 5; i_emb = 6; i_G = 7;
        i_fc1 = 8; i_fc2 = 9; i_fc3 = 10; i_fc = 11; i_ao = 12; i_b = 13;
    } else {                 // signature order
        i_wfc = 2; i_emb = 3; i_G = 4; i_fc1 = 5; i_fc2 = 6; i_fc3 = 7;
        i_fc = 8; i_ao = 9; i_b = 10; i_src = 11; i_dst = 12; i_inter = 13;
    }

    const float* feat  = (const float*)d_in[i_feat];
    const float* pos   = (const float*)d_in[i_loc];
    const int*   src   = (const int*)  d_in[i_src];
    const int*   dst   = (const int*)  d_in[i_dst];
    const int*   inter = (const int*)  d_in[i_inter];
    const float* wfc   = (const float*)d_in[i_wfc];
    const float* emb   = (const float*)d_in[i_emb];
    const float* G     = (const float*)d_in[i_G];
    const float* fc1   = (const float*)d_in[i_fc1];
    const float* fc2   = (const float*)d_in[i_fc2];
    const float* fc3   = (const float*)d_in[i_fc3];
    const float* fcF   = (const float*)d_in[i_fc];
    const float* ao    = (const float*)d_in[i_ao];
    const float* bnds  = (const float*)d_in[i_b];
    float* out = (float*)d_out;

    // order chosen so score_kernel lands in the ncu capture slot (#4)
    prep_kernel<<<12, 256>>>(fc1, fc2, fc3, fcF, G, emb);
    buildB_kernel<<<12, 256>>>(wfc);
    gemm_kernel<<<dim3(8, (NN + 127) / 128), 256>>>(feat);
    score_kernel<<<(EE + 1) / 2, 256>>>(pos, src, dst, inter, ao, bnds);
    zero_deg_kernel<<<(NN + 256) / 256, 256>>>();
    hist_kernel<<<(EE + 255) / 256, 256>>>(dst);
    scan_kernel<<<1, 1024>>>();
    scatter_kernel<<<(EE + 255) / 256, 256>>>(dst, src);
    agg_kernel<<<NN, 128>>>(out);
}

// round 4
// speedup vs baseline: 1.5818x; 1.3639x over previous
#include <cuda_runtime.h>
#include <cuda_bf16.h>
#include <math.h>

#define NN 10000
#define EE 160000
#define HH 4
#define NB 31

// ---------------- device scratch (static, no allocation) ----------------
__device__ float d_B[128 * 1024];        // combined weights: [h | Q1 | Q2 | Q3], 128 x 1024
__device__ float d_C[(size_t)NN * 1024]; // per-node: h(256) | Q1(256) | Q2(256) | Q3(256)
__device__ float d_M[12 * 64 * 64];      // M_m[h] = A_top @ F_part
__device__ float d_T[12 * 32 * 64];      // T_m[h][idx][d]
__device__ float d_sc[(size_t)EE * HH];  // per-(edge,head) attention logits
__device__ int   d_deg[NN + 1];
__device__ int   d_off[NN + 1];
__device__ int   d_cur[NN];
__device__ int   d_es[EE];               // CSR-ordered edge ids
__device__ int   d_srcs[EE];             // CSR-ordered src node ids

// ---------------- helpers ----------------
__device__ __forceinline__ float fast_tanh(float x) {
    float cx = fminf(fmaxf(x, -15.f), 15.f);
    float e  = __expf(2.f * cx);
    return __fdividef(e - 1.f, e + 1.f);
}

__device__ __forceinline__ int bucket(float x, const float* __restrict__ b) {
    // #{ i : b[i] < x }, b monotone increasing (~0.1..3.1 step 0.1), exact vs searchsorted
    int i = (int)ceilf((x - 0.1f) * 10.f);
    i = max(0, min(31, i));
    while (i > 0 && __ldg(b + i - 1) >= x) --i;
    while (i < 31 && __ldg(b + i) < x) ++i;
    return i;
}

// ---------------- CSR build ----------------
__global__ void zero_deg_kernel() {
    int i = blockIdx.x * blockDim.x + threadIdx.x;
    if (i <= NN) d_deg[i] = 0;
}

__global__ void hist_kernel(const int* __restrict__ dst) {
    int e = blockIdx.x * blockDim.x + threadIdx.x;
    if (e < EE) atomicAdd(&d_deg[dst[e]], 1);
}

// single block, 1024 threads, 10 elements/thread, warp-shfl block scan
__global__ void scan_kernel() {
    __shared__ int warpsum[32];
    int tid = threadIdx.x;
    int lane = tid & 31, wid = tid >> 5;
    int base = tid * 10;
    int loc[10];
    int s = 0;
    #pragma unroll
    for (int j = 0; j < 10; ++j) {
        int idx = base + j;
        int v = (idx < NN) ? d_deg[idx] : 0;
        loc[j] = s;
        s += v;
    }
    int x = s;
    #pragma unroll
    for (int off = 1; off < 32; off <<= 1) {
        int y = __shfl_up_sync(0xffffffffu, x, off);
        if (lane >= off) x += y;
    }
    if (lane == 31) warpsum[wid] = x;
    __syncthreads();
    if (wid == 0) {
        int t = warpsum[lane];
        #pragma unroll
        for (int off = 1; off < 32; off <<= 1) {
            int y = __shfl_up_sync(0xffffffffu, t, off);
            if (lane >= off) t += y;
        }
        warpsum[lane] = t;
    }
    __syncthreads();
    int warpbase = (wid > 0) ? warpsum[wid - 1] : 0;
    int excl = warpbase + x - s;
    #pragma unroll
    for (int j = 0; j < 10; ++j) {
        int idx = base + j;
        if (idx < NN) { d_off[idx] = excl + loc[j]; d_cur[idx] = excl + loc[j]; }
    }
    if (tid == 0) d_off[NN] = warpsum[31];
}

__global__ void scatter_kernel(const int* __restrict__ dst, const int* __restrict__ src) {
    int e = blockIdx.x * blockDim.x + threadIdx.x;
    if (e < EE) {
        int p = atomicAdd(&d_cur[dst[e]], 1);
        d_es[p] = e;
        d_srcs[p] = src[e];
    }
}

// ---------------- precompute M and T (12 blocks = m*4+h) ----------------
__global__ void prep_kernel(const float* __restrict__ fc1, const float* __restrict__ fc2,
                            const float* __restrict__ fc3, const float* __restrict__ fcF,
                            const float* __restrict__ G, const float* __restrict__ emb) {
    int bx = blockIdx.x;
    int m = bx / HH, h = bx % HH;
    const float* A = (m == 0 ? fc1 : (m == 1 ? fc2 : fc3)) + (size_t)h * 128 * 64;
    const float* F = fcF + (size_t)h * 192 * 64 + (size_t)m * 64 * 64;
    __shared__ float sAF[64 * 64];
    __shared__ float sGA[32 * 64];
    int tid = threadIdx.x;

    for (int o = tid; o < 64 * 64; o += 256) {  // M = A_top @ F
        int k = o >> 6, d = o & 63;
        float acc = 0.f;
        for (int c = 0; c < 64; ++c) acc += A[k * 64 + c] * F[c * 64 + d];
        d_M[bx * 4096 + o] = acc;
    }
    for (int o = tid; o < 64 * 64; o += 256) {  // AF = A_bot @ F
        int j = o >> 6, d = o & 63;
        float acc = 0.f;
        for (int c = 0; c < 64; ++c) acc += A[(64 + j) * 64 + c] * F[c * 64 + d];
        sAF[o] = acc;
    }
    __syncthreads();
    const float* Gh = G + (size_t)h * 32 * 64;  // GA = G[h] @ AF
    for (int o = tid; o < 32 * 64; o += 256) {
        int k = o >> 6, d = o & 63;
        float acc = 0.f;
        for (int j = 0; j < 64; ++j) acc += Gh[k * 64 + j] * sAF[j * 64 + d];
        sGA[o] = acc;
    }
    __syncthreads();
    for (int o = tid; o < 32 * 64; o += 256) {  // T = embed @ GA
        int i = o >> 6, d = o & 63;
        float acc = 0.f;
        for (int k = 0; k < 32; ++k) acc += emb[i * 32 + k] * sGA[k * 64 + d];
        d_T[bx * 2048 + o] = acc;
    }
}

// ---------------- build combined B = [W_fc | W_fc@M1 | W_fc@M2 | W_fc@M3] ----------------
__global__ void buildB_kernel(const float* __restrict__ wfc) {
    int bx = blockIdx.x;
    int m = bx / HH, h = bx % HH;
    const float* M = d_M + bx * 4096;
    int tid = threadIdx.x;
    for (int o = tid; o < 128 * 64; o += 256) {
        int k = o >> 6, d = o & 63;
        float acc = 0.f;
        for (int j = 0; j < 64; ++j) acc += wfc[k * 256 + h * 64 + j] * M[j * 64 + d];
        d_B[k * 1024 + 256 + m * 256 + h * 64 + d] = acc;
    }
    if (m == 0) {
        for (int o = tid; o < 128 * 64; o += 256) {
            int k = o >> 6, d = o & 63;
            d_B[k * 1024 + h * 64 + d] = wfc[k * 256 + h * 64 + d];
        }
    }
}

// ---------------- node GEMM: C[N,1024] = feat[N,128] @ B[128,1024] ----------------
__global__ void __launch_bounds__(256, 2) gemm_kernel(const float* __restrict__ A) {
    __shared__ float As[16][128];
    __shared__ float Bs[16][128];
    int bx = blockIdx.x;
    int by = blockIdx.y;
    int tid = threadIdx.x;
    int tx = tid & 15, ty = tid >> 4;
    float acc[8][8] = {};
    int rowBase = by * 128;
    for (int k0 = 0; k0 < 128; k0 += 16) {
        {
            int r = tid >> 1;
            int c = (tid & 1) * 8;
            int row = rowBase + r;
            float4 v0, v1;
            if (row < NN) {
                v0 = *(const float4*)(A + (size_t)row * 128 + k0 + c);
                v1 = *(const float4*)(A + (size_t)row * 128 + k0 + c + 4);
            } else {
                v0 = make_float4(0.f, 0.f, 0.f, 0.f);
                v1 = v0;
            }
            As[c + 0][r] = v0.x; As[c + 1][r] = v0.y; As[c + 2][r] = v0.z; As[c + 3][r] = v0.w;
            As[c + 4][r] = v1.x; As[c + 5][r] = v1.y; As[c + 6][r] = v1.z; As[c + 7][r] = v1.w;
        }
        {
            int i = tid * 8;
            int r = i >> 7, c = i & 127;
            const float* src = d_B + (size_t)(k0 + r) * 1024 + bx * 128 + c;
            float4 v0 = *(const float4*)(src);
            float4 v1 = *(const float4*)(src + 4);
            *(float4*)(&Bs[r][c]) = v0;
            *(float4*)(&Bs[r][c + 4]) = v1;
        }
        __syncthreads();
        #pragma unroll
        for (int k = 0; k < 16; ++k) {
            float a[8], b[8];
            *(float4*)(a)     = *(const float4*)(&As[k][ty * 8]);
            *(float4*)(a + 4) = *(const float4*)(&As[k][ty * 8 + 4]);
            *(float4*)(b)     = *(const float4*)(&Bs[k][tx * 8]);
            *(float4*)(b + 4) = *(const float4*)(&Bs[k][tx * 8 + 4]);
            #pragma unroll
            for (int i = 0; i < 8; ++i)
                #pragma unroll
                for (int j = 0; j < 8; ++j) acc[i][j] += a[i] * b[j];
        }
        __syncthreads();
    }
    #pragma unroll
    for (int i = 0; i < 8; ++i) {
        int row = rowBase + ty * 8 + i;
        if (row < NN) {
            float* dstp = d_C + (size_t)row * 1024 + bx * 128 + tx * 8;
            *(float4*)(dstp)     = make_float4(acc[i][0], acc[i][1], acc[i][2], acc[i][3]);
            *(float4*)(dstp + 4) = make_float4(acc[i][4], acc[i][5], acc[i][6], acc[i][7]);
        }
    }
}

// ---------------- score kernel: ONE WARP PER EDGE, all 4 heads ----------------
// Lanes 0..8 compute the 9 (distance,bucket) pairs in parallel; broadcast via shfl.
__global__ void score_kernel(const float* __restrict__ pos, const int* __restrict__ srcA,
                             const int* __restrict__ dstA, const int* __restrict__ interA,
                             const float* __restrict__ ao, const float* __restrict__ bnds) {
    int e = (blockIdx.x * blockDim.x + threadIdx.x) >> 5;
    int lane = threadIdx.x & 31;
    if (e >= EE) return;

    int s = __ldg(srcA + e);
    int v = __ldg(dstA + e);
    int4 itv = __ldg((const int4*)interA + e);

    // --- parallel distance + bucket: lane j in 0..8 handles pair j ---
    // j=0: (v,s) -> d1; j=1..4: (v, it[j-1]) -> d2_h; j=5..8: (s, it[j-5]) -> d3_h
    int j = min(lane, 8);
    int aid = (j >= 5) ? s : v;
    int k = (j >= 5) ? (j - 5) : (j - 1);   // -1 for j==0 (unused)
    int bid = s;
    if (j >= 1) {
        bid = (k == 0) ? itv.x : ((k == 1) ? itv.y : ((k == 2) ? itv.z : itv.w));
    }
    float ax = __ldg(pos + (size_t)aid * 3 + 0);
    float ay = __ldg(pos + (size_t)aid * 3 + 1);
    float az = __ldg(pos + (size_t)aid * 3 + 2);
    float bxp = __ldg(pos + (size_t)bid * 3 + 0);
    float byp = __ldg(pos + (size_t)bid * 3 + 1);
    float bzp = __ldg(pos + (size_t)bid * 3 + 2);
    float dd = sqrtf((ax - bxp) * (ax - bxp) + (ay - byp) * (ay - byp) + (az - bzp) * (az - bzp));
    int bkt = bucket(dd, bnds);

    int i1 = __shfl_sync(0xffffffffu, bkt, 0);
    int i2_0 = __shfl_sync(0xffffffffu, bkt, 1);
    int i2_1 = __shfl_sync(0xffffffffu, bkt, 2);
    int i2_2 = __shfl_sync(0xffffffffu, bkt, 3);
    int i2_3 = __shfl_sync(0xffffffffu, bkt, 4);
    int i3_0 = __shfl_sync(0xffffffffu, bkt, 5);
    int i3_1 = __shfl_sync(0xffffffffu, bkt, 6);
    int i3_2 = __shfl_sync(0xffffffffu, bkt, 7);
    int i3_3 = __shfl_sync(0xffffffffu, bkt, 8);

    const float* Cs = d_C + (size_t)s * 1024;
    const float* Cv = d_C + (size_t)v * 1024;

    float acc0, acc1, acc2, acc3;
    #define HEAD_SCORE(h, ITN, I2, I3, ACC) {                                              \
        const float* Ci = d_C + (size_t)(ITN) * 1024;                                       \
        float2 q1 = __ldg((const float2*)(Cs + 256 + (h) * 64) + lane);                     \
        float2 q2 = __ldg((const float2*)(Ci + 512 + (h) * 64) + lane);                     \
        float2 q3 = __ldg((const float2*)(Cv + 768 + (h) * 64) + lane);                     \
        float2 t1 = __ldg((const float2*)(d_T + ((0 * HH + (h)) * 32 + i1) * 64) + lane);   \
        float2 t2 = __ldg((const float2*)(d_T + ((1 * HH + (h)) * 32 + (I2)) * 64) + lane); \
        float2 t3 = __ldg((const float2*)(d_T + ((2 * HH + (h)) * 32 + (I3)) * 64) + lane); \
        float2 av = __ldg((const float2*)(ao + (h) * 64) + lane);                           \
        float zx = q1.x + q2.x + q3.x + t1.x + t2.x + t3.x;                                 \
        float zy = q1.y + q2.y + q3.y + t1.y + t2.y + t3.y;                                 \
        ACC = fast_tanh(zx) * av.x + fast_tanh(zy) * av.y;                                  \
    }
    HEAD_SCORE(0, itv.x, i2_0, i3_0, acc0)
    HEAD_SCORE(1, itv.y, i2_1, i3_1, acc1)
    HEAD_SCORE(2, itv.z, i2_2, i3_2, acc2)
    HEAD_SCORE(3, itv.w, i2_3, i3_3, acc3)
    #undef HEAD_SCORE

    #pragma unroll
    for (int o = 16; o > 0; o >>= 1) {
        acc0 += __shfl_xor_sync(0xffffffffu, acc0, o);
        acc1 += __shfl_xor_sync(0xffffffffu, acc1, o);
        acc2 += __shfl_xor_sync(0xffffffffu, acc2, o);
        acc3 += __shfl_xor_sync(0xffffffffu, acc3, o);
    }
    if (lane == 0)
        *(float4*)(d_sc + (size_t)e * HH) = make_float4(acc0, acc1, acc2, acc3);
}

// ---------------- aggregation: one block per dst, one warp per head ----------------
__global__ void agg_kernel(float* __restrict__ out) {
    int v = blockIdx.x;
    int tid = threadIdx.x;
    int h = tid >> 5, lane = tid & 31;
    __shared__ float sFT[4][64];

    int beg = d_off[v], end = d_off[v + 1];

    float mx = -3.4e38f, den = 0.f;
    float accx = 0.f, accy = 0.f;

    for (int c = beg; c < end; c += 32) {
        int n = min(32, end - c);
        int sL = 0; float scL = 0.f;
        if (lane < n) {
            int eL = d_es[c + lane];
            sL = d_srcs[c + lane];
            scL = d_sc[(size_t)eL * HH + h];
        }
        for (int jj = 0; jj < n; ++jj) {
            int s    = __shfl_sync(0xffffffffu, sL, jj);
            float sc = __shfl_sync(0xffffffffu, scL, jj);
            float2 hs = ((const float2*)(d_C + (size_t)s * 1024 + h * 64))[lane];
            float nm = fmaxf(mx, sc);
            float scale = __expf(mx - nm);
            float w = __expf(sc - nm);
            den  = den  * scale + w;
            accx = accx * scale + w * hs.x;
            accy = accy * scale + w * hs.y;
            mx = nm;
        }
    }

    float inv = (den > 0.f) ? 1.0f / den : 0.f;
    sFT[h][lane * 2 + 0] = accx * inv;
    sFT[h][lane * 2 + 1] = accy * inv;
    __syncthreads();
    if (tid < 64)
        out[(size_t)v * 64 + tid] = 0.25f * (sFT[0][tid] + sFT[1][tid] + sFT[2][tid] + sFT[3][tid]);
}

// ---------------- launch ----------------
extern "C" void kernel_launch(void* const* d_in, const int* in_sizes, int n_in,
                              void* d_out, int out_size) {
    int i_feat = 0, i_loc = 1, i_src, i_dst, i_inter, i_wfc, i_emb, i_G,
        i_fc1, i_fc2, i_fc3, i_fc, i_ao, i_b;
    if (in_sizes[2] == EE) { // dict order
        i_src = 2; i_dst = 3; i_inter = 4; i_wfc = 5; i_emb = 6; i_G = 7;
        i_fc1 = 8; i_fc2 = 9; i_fc3 = 10; i_fc = 11; i_ao = 12; i_b = 13;
    } else {                 // signature order
        i_wfc = 2; i_emb = 3; i_G = 4; i_fc1 = 5; i_fc2 = 6; i_fc3 = 7;
        i_fc = 8; i_ao = 9; i_b = 10; i_src = 11; i_dst = 12; i_inter = 13;
    }

    const float* feat  = (const float*)d_in[i_feat];
    const float* pos   = (const float*)d_in[i_loc];
    const int*   src   = (const int*)  d_in[i_src];
    const int*   dst   = (const int*)  d_in[i_dst];
    const int*   inter = (const int*)  d_in[i_inter];
    const float* wfc   = (const float*)d_in[i_wfc];
    const float* emb   = (const float*)d_in[i_emb];
    const float* G     = (const float*)d_in[i_G];
    const float* fc1   = (const float*)d_in[i_fc1];
    const float* fc2   = (const float*)d_in[i_fc2];
    const float* fc3   = (const float*)d_in[i_fc3];
    const float* fcF   = (const float*)d_in[i_fc];
    const float* ao    = (const float*)d_in[i_ao];
    const float* bnds  = (const float*)d_in[i_b];
    float* out = (float*)d_out;

    // order chosen so score_kernel lands in the ncu capture slot (4th launch)
    prep_kernel<<<12, 256>>>(fc1, fc2, fc3, fcF, G, emb);
    buildB_kernel<<<12, 256>>>(wfc);
    gemm_kernel<<<dim3(8, (NN + 127) / 128), 256>>>(feat);
    score_kernel<<<(EE + 7) / 8, 256>>>(pos, src, dst, inter, ao, bnds);
    zero_deg_kernel<<<(NN + 256) / 256, 256>>>();
    hist_kernel<<<(EE + 255) / 256, 256>>>(dst);
    scan_kernel<<<1, 1024>>>();
    scatter_kernel<<<(EE + 255) / 256, 256>>>(dst, src);
    agg_kernel<<<NN, 128>>>(out);
}